// round 1
// baseline (speedup 1.0000x reference)
#include <cuda_runtime.h>
#include <cstdint>

#define HID 128
#define T_STEPS 2048
#define BATCH 64
#define NOUT 5
#define MROWS (BATCH * T_STEPS)   // 131072

// -------------------- scratch (device globals; no allocation) --------------------
__device__ float g_xw[(size_t)MROWS * 384];   // input-projection buffer  (201 MB)
__device__ float g_h0[(size_t)MROWS * HID];   // layer output ping        (67 MB)
__device__ float g_h1[(size_t)MROWS * HID];   // layer output pong        (67 MB)

// -------------------- packed f32x2 helpers --------------------
__device__ __forceinline__ unsigned long long pack2(float lo, float hi) {
    unsigned long long r;
    asm("mov.b64 %0, {%1, %2};" : "=l"(r) : "f"(lo), "f"(hi));
    return r;
}
__device__ __forceinline__ void unpack2(unsigned long long v, float& lo, float& hi) {
    asm("mov.b64 {%0, %1}, %2;" : "=f"(lo), "=f"(hi) : "l"(v));
}
#define FMA2(d, a, b, c) \
    asm("fma.rn.f32x2 %0, %1, %2, %3;" : "=l"(d) : "l"(a), "l"(b), "l"(c))

// ============================================================================
// GEMM: C[M,384-tile] = A[M,128] @ W[128,384] + bias   (BM=128, BN=128, BK=128)
// grid = (M/128, 3), 256 threads, dynamic smem = As(128x132) + Bs(128x128)
// ============================================================================
__global__ __launch_bounds__(256, 1)
void gemm128(const float* __restrict__ A, const float* __restrict__ W,
             const float* __restrict__ bias, float* __restrict__ C, int M) {
    extern __shared__ float smem[];
    float* As = smem;              // As[k][m], pitch 132
    float* Bs = smem + 128 * 132;  // Bs[k][n], pitch 128

    const int m0 = blockIdx.x * 128;
    const int n0 = blockIdx.y * 128;
    const int tid = threadIdx.x;

    // Load A tile (transposed into As[k][m])
    for (int idx = tid; idx < 128 * 32; idx += 256) {
        int r = idx >> 5, c4 = idx & 31;
        float4 v = *(const float4*)(A + (size_t)(m0 + r) * 128 + c4 * 4);
        As[(c4 * 4 + 0) * 132 + r] = v.x;
        As[(c4 * 4 + 1) * 132 + r] = v.y;
        As[(c4 * 4 + 2) * 132 + r] = v.z;
        As[(c4 * 4 + 3) * 132 + r] = v.w;
    }
    // Load W tile (row-major Bs[k][n])
    for (int idx = tid; idx < 128 * 32; idx += 256) {
        int k = idx >> 5, c4 = idx & 31;
        *(float4*)&Bs[k * 128 + c4 * 4] =
            *(const float4*)(W + (size_t)k * 384 + n0 + c4 * 4);
    }
    __syncthreads();

    const int tx = tid & 15, ty = tid >> 4;
    const int mr = ty * 8, nc = tx * 8;

    unsigned long long acc[8][4];
#pragma unroll
    for (int i = 0; i < 8; i++)
#pragma unroll
        for (int jj = 0; jj < 4; jj++) acc[i][jj] = 0ULL;

#pragma unroll 8
    for (int k = 0; k < 128; k++) {
        float4 a0 = *(const float4*)&As[k * 132 + mr];
        float4 a1 = *(const float4*)&As[k * 132 + mr + 4];
        ulonglong2 b0 = *(const ulonglong2*)&Bs[k * 128 + nc];
        ulonglong2 b1 = *(const ulonglong2*)&Bs[k * 128 + nc + 4];
        float av[8] = {a0.x, a0.y, a0.z, a0.w, a1.x, a1.y, a1.z, a1.w};
        unsigned long long bp[4] = {b0.x, b0.y, b1.x, b1.y};
#pragma unroll
        for (int i = 0; i < 8; i++) {
            unsigned long long ap = pack2(av[i], av[i]);
#pragma unroll
            for (int jj = 0; jj < 4; jj++) FMA2(acc[i][jj], ap, bp[jj], acc[i][jj]);
        }
    }

    float bv[8];
#pragma unroll
    for (int c = 0; c < 8; c++) bv[c] = bias[n0 + nc + c];

#pragma unroll
    for (int i = 0; i < 8; i++) {
        float o[8];
#pragma unroll
        for (int jj = 0; jj < 4; jj++) unpack2(acc[i][jj], o[2 * jj], o[2 * jj + 1]);
#pragma unroll
        for (int c = 0; c < 8; c++) o[c] += bv[c];
        float* cp = C + (size_t)(m0 + mr + i) * 384 + n0 + nc;
        *(float4*)cp = make_float4(o[0], o[1], o[2], o[3]);
        *(float4*)(cp + 4) = make_float4(o[4], o[5], o[6], o[7]);
    }
}

// ============================================================================
// GRU scan: one CTA per batch, 384 threads (thread j owns rk column j in regs).
// xw: [B*T, 384] precomputed input projection (incl. input bias).
// hout: [B*T, 128] layer output.
// ============================================================================
__global__ __launch_bounds__(384, 1)
void scan_kernel(const float* __restrict__ xw, const float* __restrict__ rk,
                 const float* __restrict__ brec, float* __restrict__ hout) {
    const int b = blockIdx.x;
    const int j = threadIdx.x;

    __shared__ __align__(16) float h_sh[HID];
    __shared__ float g_sh[384];
    __shared__ float xh_sh[HID];

    // Recurrent weight column j -> 64 packed f32x2 register pairs
    unsigned long long w2[64];
#pragma unroll
    for (int i = 0; i < 64; i++) {
        float a0 = rk[(size_t)(2 * i) * 384 + j];
        float a1 = rk[(size_t)(2 * i + 1) * 384 + j];
        w2[i] = pack2(a0, a1);
    }
    const float bj = brec[j];

    if (j < HID) h_sh[j] = 0.0f;
    const float* xrow = xw + (size_t)b * T_STEPS * 384 + j;
    float xv = xrow[0];
    __syncthreads();

    for (int t = 0; t < T_STEPS; t++) {
        float xv_next = (t + 1 < T_STEPS) ? xrow[(size_t)(t + 1) * 384] : 0.0f;

        // dot(h, rk[:,j])  -- h broadcast from smem, weights in regs
        unsigned long long acc = 0ULL;
        const ulonglong2* hp = (const ulonglong2*)h_sh;
#pragma unroll
        for (int i = 0; i < 32; i++) {
            ulonglong2 hv = hp[i];
            FMA2(acc, hv.x, w2[2 * i], acc);
            FMA2(acc, hv.y, w2[2 * i + 1], acc);
        }
        float lo, hi;
        unpack2(acc, lo, hi);
        float ri = lo + hi + bj;  // recurrent part incl. recurrent bias

        if (j < 256) {
            g_sh[j] = ri + xv;        // z and r gates: x-part + recurrent part
        } else {
            g_sh[j] = ri;             // h-gate recurrent part stays separate
            xh_sh[j - 256] = xv;      // h-gate x-part
        }
        __syncthreads();

        if (j < HID) {
            float z = 1.0f / (1.0f + expf(-g_sh[j]));
            float r = 1.0f / (1.0f + expf(-g_sh[HID + j]));
            float hh = tanhf(xh_sh[j] + r * g_sh[2 * HID + j]);
            float hold = h_sh[j];
            float hn = z * hold + (1.0f - z) * hh;
            h_sh[j] = hn;
            hout[((size_t)b * T_STEPS + t) * HID + j] = hn;
        }
        xv = xv_next;
        __syncthreads();
    }
}

// ============================================================================
// Output head: out[M,5] = H[M,128] @ wo[128,5] + bo
// ============================================================================
__global__ __launch_bounds__(256, 1)
void outproj(const float* __restrict__ H, const float* __restrict__ wo,
             const float* __restrict__ bo, float* __restrict__ out, int M) {
    __shared__ float ws[HID * NOUT];
    __shared__ float bs[NOUT];
    for (int i = threadIdx.x; i < HID * NOUT; i += blockDim.x) ws[i] = wo[i];
    if (threadIdx.x < NOUT) bs[threadIdx.x] = bo[threadIdx.x];
    __syncthreads();

    int r = blockIdx.x * blockDim.x + threadIdx.x;
    if (r >= M) return;

    const float4* hr = (const float4*)(H + (size_t)r * HID);
    float acc[NOUT];
#pragma unroll
    for (int o = 0; o < NOUT; o++) acc[o] = bs[o];

#pragma unroll
    for (int k4 = 0; k4 < 32; k4++) {
        float4 v = hr[k4];
#pragma unroll
        for (int o = 0; o < NOUT; o++) {
            acc[o] += v.x * ws[(k4 * 4 + 0) * NOUT + o];
            acc[o] += v.y * ws[(k4 * 4 + 1) * NOUT + o];
            acc[o] += v.z * ws[(k4 * 4 + 2) * NOUT + o];
            acc[o] += v.w * ws[(k4 * 4 + 3) * NOUT + o];
        }
    }
#pragma unroll
    for (int o = 0; o < NOUT; o++) out[(size_t)r * NOUT + o] = acc[o];
}

// ============================================================================
extern "C" void kernel_launch(void* const* d_in, const int* in_sizes, int n_in,
                              void* d_out, int out_size) {
    const float* x   = (const float*)d_in[0];
    const float* k0  = (const float*)d_in[1];
    const float* rk0 = (const float*)d_in[2];
    const float* b0  = (const float*)d_in[3];
    const float* k1  = (const float*)d_in[4];
    const float* rk1 = (const float*)d_in[5];
    const float* b1  = (const float*)d_in[6];
    const float* k2  = (const float*)d_in[7];
    const float* rk2 = (const float*)d_in[8];
    const float* b2  = (const float*)d_in[9];
    const float* wo  = (const float*)d_in[10];
    const float* bo  = (const float*)d_in[11];
    float* out = (float*)d_out;

    float *xwp, *h0p, *h1p;
    cudaGetSymbolAddress((void**)&xwp, g_xw);
    cudaGetSymbolAddress((void**)&h0p, g_h0);
    cudaGetSymbolAddress((void**)&h1p, g_h1);

    const int M = MROWS;
    const size_t smem = (128 * 132 + 128 * 128) * sizeof(float);  // 133 KB
    cudaFuncSetAttribute(gemm128, cudaFuncAttributeMaxDynamicSharedMemorySize,
                         (int)smem);

    dim3 ggrid(M / 128, 3);

    // Layer 0
    gemm128<<<ggrid, 256, smem>>>(x, k0, b0, xwp, M);
    scan_kernel<<<BATCH, 384>>>(xwp, rk0, b0 + 384, h0p);
    // Layer 1
    gemm128<<<ggrid, 256, smem>>>(h0p, k1, b1, xwp, M);
    scan_kernel<<<BATCH, 384>>>(xwp, rk1, b1 + 384, h1p);
    // Layer 2
    gemm128<<<ggrid, 256, smem>>>(h1p, k2, b2, xwp, M);
    scan_kernel<<<BATCH, 384>>>(xwp, rk2, b2 + 384, h0p);
    // Output head
    outproj<<<(M + 255) / 256, 256>>>(h0p, wo, bo, out, M);
}